// round 5
// baseline (speedup 1.0000x reference)
#include <cuda_runtime.h>
#include <cuda_bf16.h>
#include <math.h>

#define QLEN   2048
#define HID    4096
#define NHEADS 32
#define ROWS   (NHEADS * QLEN)      // 65536
#define NCHUNK 1024
#define RPC    (ROWS / NCHUNK)      // 64 rows per chunk
#define ROWF4  (QLEN / 4)           // 512 float4 per row

// ---- scratch ----
__device__ float              g_partial[NCHUNK][QLEN];   // 8 MB
__device__ unsigned long long g_key[QLEN];
__device__ int                g_flag[QLEN];
__device__ int                g_keep[QLEN];
__device__ int                g_nkeep;

__device__ __forceinline__ unsigned long long dkey(double d) {
    unsigned long long u = __double_as_longlong(d);
    return (u & 0x8000000000000000ull) ? ~u : (u | 0x8000000000000000ull);
}

// K1: contiguous-streaming partial column sums.
// grid = NCHUNK, block = 512 (one full 8KB row per iteration; rows contiguous).
__global__ void __launch_bounds__(512, 2) k_partial(const float* __restrict__ w) {
    const int t = threadIdx.x;                    // float4 lane within row
    const float4* p = reinterpret_cast<const float4*>(w)
                    + (size_t)blockIdx.x * RPC * ROWF4 + t;
    float4 a0 = make_float4(0.f,0.f,0.f,0.f);
    float4 a1 = make_float4(0.f,0.f,0.f,0.f);
#pragma unroll
    for (int r = 0; r < RPC; r += 8) {
        float4 v[8];
#pragma unroll
        for (int j = 0; j < 8; ++j)
            v[j] = __ldcs(p + (size_t)(r + j) * ROWF4);
#pragma unroll
        for (int j = 0; j < 8; j += 2) {
            a0.x += v[j].x;   a0.y += v[j].y;   a0.z += v[j].z;   a0.w += v[j].w;
            a1.x += v[j+1].x; a1.y += v[j+1].y; a1.z += v[j+1].z; a1.w += v[j+1].w;
        }
    }
    float4 s;
    s.x = a0.x + a1.x; s.y = a0.y + a1.y; s.z = a0.z + a1.z; s.w = a0.w + a1.w;
    *reinterpret_cast<float4*>(&g_partial[blockIdx.x][t * 4]) = s;
}

// K1b: finalize in double, 8 independent accumulators. grid = 8, block = 256.
__global__ void k_finalize() {
    const int col = blockIdx.x * blockDim.x + threadIdx.x;
    double a[8] = {0,0,0,0,0,0,0,0};
#pragma unroll 4
    for (int c = 0; c < NCHUNK; c += 8) {
#pragma unroll
        for (int q = 0; q < 8; ++q) a[q] += (double)g_partial[c + q][col];
    }
    double s = ((a[0]+a[1]) + (a[2]+a[3])) + ((a[4]+a[5]) + (a[6]+a[7]));
    g_key[col] = dkey(s);
}

// K2a: rank counting, keys staged in smem. grid = QLEN/8, block = 256.
__global__ void k_rank(const int* __restrict__ startp, const int* __restrict__ lenp) {
    __shared__ unsigned long long sk[QLEN];
    const int start = *startp;
    const int ilen  = *lenp;
    const int t = threadIdx.x;
    for (int i = t; i < ilen; i += 256) sk[i] = g_key[start + i];
    __syncthreads();
    const int w = t >> 5, lane = t & 31;
    const int p = blockIdx.x * 8 + w;
    if (p >= QLEN) return;
    if (p < start || p >= start + ilen) {
        if (lane == 0) g_flag[p] = 1;
        return;
    }
    const int keep_k = (int)llrint((double)ilen * (1.0 - 0.3));
    const int i = p - start;
    const unsigned long long v = sk[i];
    int c = 0;
    for (int j = lane; j < ilen; j += 32) {
        const unsigned long long u = sk[j];
        c += (u > v) || (u == v && j < i);
    }
#pragma unroll
    for (int off = 16; off; off >>= 1) c += __shfl_down_sync(0xffffffffu, c, off);
    if (lane == 0) g_flag[p] = (c < keep_k) ? 1 : 0;
}

// K2b: compact via shuffle scan. single block, 1024 threads, 2 elems/thread.
__global__ void k_compact() {
    const int t = threadIdx.x;
    const int lane = t & 31, w = t >> 5;
    const int f0 = g_flag[2 * t];
    const int f1 = g_flag[2 * t + 1];
    const int sum = f0 + f1;
    int v = sum;
#pragma unroll
    for (int o = 1; o < 32; o <<= 1) {
        int n = __shfl_up_sync(0xffffffffu, v, o);
        if (lane >= o) v += n;
    }
    __shared__ int wsum[32];
    if (lane == 31) wsum[w] = v;
    __syncthreads();
    if (w == 0) {
        int x = wsum[lane];
#pragma unroll
        for (int o = 1; o < 32; o <<= 1) {
            int n = __shfl_up_sync(0xffffffffu, x, o);
            if (lane >= o) x += n;
        }
        wsum[lane] = x;
    }
    __syncthreads();
    const int base = (w ? wsum[w - 1] : 0) + v - sum;
    if (f0) g_keep[base] = 2 * t;
    if (f1) g_keep[base + f0] = 2 * t + 1;
    if (t == 1023) g_nkeep = wsum[31];
}

// K3: gather hs / pe rows. grid = (QLEN, 2), block = 256.
__global__ void k_gather_rows(const float* __restrict__ hs,
                              const float* __restrict__ pe,
                              float* __restrict__ out) {
    const int nk = g_nkeep;
    const int r  = blockIdx.x;
    if (r >= nk) return;
    const int srcrow = g_keep[r];
    const float* sp = (blockIdx.y ? pe : hs) + (size_t)srcrow * HID;
    float* dp = out + (size_t)blockIdx.y * nk * HID + (size_t)r * HID;
    const float4* s4 = reinterpret_cast<const float4*>(sp);
    float4* d4 = reinterpret_cast<float4*>(dp);
#pragma unroll 4
    for (int i = threadIdx.x; i < HID / 4; i += 256) d4[i] = s4[i];
}

// K4: mask gather, smem-staged source row. grid = QLEN, block = 512.
__global__ void k_gather_mask(const float* __restrict__ mask,
                              float* __restrict__ out) {
    __shared__ float srow[QLEN];
    const int nk = g_nkeep;
    const int r = blockIdx.x;
    if (r >= nk) return;
    const int t = threadIdx.x;
    const float* mp = mask + (size_t)g_keep[r] * QLEN;
#pragma unroll
    for (int i = t; i < QLEN; i += 512) srow[i] = mp[i];
    __syncthreads();
    const size_t base = 2ull * (size_t)nk * HID + (size_t)r * nk;
    for (int c = t; c < nk; c += 512)
        out[base + c] = srow[g_keep[c]];
}

extern "C" void kernel_launch(void* const* d_in, const int* in_sizes, int n_in,
                              void* d_out, int out_size) {
    const float* hs   = (const float*)d_in[0];
    const float* pe   = (const float*)d_in[1];
    const float* mask = (const float*)d_in[2];
    const float* attn = (const float*)d_in[3];
    const int* startp = (const int*)d_in[4];
    const int* lenp   = (const int*)d_in[5];
    float* out = (float*)d_out;

    k_partial<<<NCHUNK, 512>>>(attn);
    k_finalize<<<QLEN / 256, 256>>>();
    k_rank<<<QLEN / 8, 256>>>(startp, lenp);
    k_compact<<<1, 1024>>>();
    dim3 g3(QLEN, 2);
    k_gather_rows<<<g3, 256>>>(hs, pe, out);
    k_gather_mask<<<QLEN, 512>>>(mask, out);
}

// round 7
// speedup vs baseline: 2.7954x; 2.7954x over previous
#include <cuda_runtime.h>
#include <cuda_bf16.h>
#include <math.h>

#define QLEN   2048
#define HID    4096
#define NHEADS 32
#define ROWS   (NHEADS * QLEN)      // 65536
#define RPC    32                   // rows per chunk (contiguous 256KB stream)
#define NCHUNK (ROWS / RPC)         // 2048
#define ROWF4  (QLEN / 4)           // 512 float4 per row
#define NSLICE 32                   // finalize stage-a slices (64 chunks each)

// ---- scratch ----
__device__ float              g_partial[NCHUNK][QLEN];   // 16 MB
__device__ double             g_pd[NSLICE][QLEN];        // 512 KB
__device__ unsigned long long g_key[QLEN];
__device__ int                g_flag[QLEN];
__device__ int                g_keep[QLEN];
__device__ int                g_nkeep;

__device__ __forceinline__ unsigned long long dkey(double d) {
    unsigned long long u = __double_as_longlong(d);
    return (u & 0x8000000000000000ull) ? ~u : (u | 0x8000000000000000ull);
}

// K1: contiguous-streaming partial sums, gather_rows-style.
// grid = NCHUNK (2048), block = 512. Block streams 32 contiguous rows (256KB).
// Plain LDG.128, 4-deep batches, dual accumulators, no launch_bounds.
__global__ void k_partial(const float* __restrict__ w) {
    const int t = threadIdx.x;                   // float4 lane within row
    const float4* p = reinterpret_cast<const float4*>(w)
                    + (size_t)blockIdx.x * RPC * ROWF4 + t;
    float4 a0 = make_float4(0.f,0.f,0.f,0.f);
    float4 a1 = make_float4(0.f,0.f,0.f,0.f);
#pragma unroll
    for (int r = 0; r < RPC; r += 4) {
        float4 v0 = p[(size_t)(r + 0) * ROWF4];
        float4 v1 = p[(size_t)(r + 1) * ROWF4];
        float4 v2 = p[(size_t)(r + 2) * ROWF4];
        float4 v3 = p[(size_t)(r + 3) * ROWF4];
        a0.x += v0.x; a0.y += v0.y; a0.z += v0.z; a0.w += v0.w;
        a1.x += v1.x; a1.y += v1.y; a1.z += v1.z; a1.w += v1.w;
        a0.x += v2.x; a0.y += v2.y; a0.z += v2.z; a0.w += v2.w;
        a1.x += v3.x; a1.y += v3.y; a1.z += v3.z; a1.w += v3.w;
    }
    float4 s;
    s.x = a0.x + a1.x; s.y = a0.y + a1.y; s.z = a0.z + a1.z; s.w = a0.w + a1.w;
    *reinterpret_cast<float4*>(&g_partial[blockIdx.x][t * 4]) = s;
}

// K1b-a: reduce 2048 chunk-partials -> 32 slice-partials (double).
// grid = 256, block = 256 (65536 threads: col = g&2047, slice = g>>11).
__global__ void k_finalize_a() {
    const int g = blockIdx.x * 256 + threadIdx.x;
    const int col = g & (QLEN - 1);
    const int sl  = g >> 11;
    const int c0  = sl * (NCHUNK / NSLICE);      // 64 chunks per slice
    double a[8] = {0,0,0,0,0,0,0,0};
#pragma unroll
    for (int c = 0; c < NCHUNK / NSLICE; c += 8) {
#pragma unroll
        for (int q = 0; q < 8; ++q) a[q] += (double)g_partial[c0 + c + q][col];
    }
    g_pd[sl][col] = ((a[0]+a[1]) + (a[2]+a[3])) + ((a[4]+a[5]) + (a[6]+a[7]));
}

// K1b-b: reduce 32 slice-partials -> key. grid = 8, block = 256.
__global__ void k_finalize_b() {
    const int col = blockIdx.x * 256 + threadIdx.x;
    double a[8] = {0,0,0,0,0,0,0,0};
#pragma unroll
    for (int s = 0; s < NSLICE; s += 8) {
#pragma unroll
        for (int q = 0; q < 8; ++q) a[q] += g_pd[s + q][col];
    }
    double s = ((a[0]+a[1]) + (a[2]+a[3])) + ((a[4]+a[5]) + (a[6]+a[7]));
    g_key[col] = dkey(s);
}

// K2a: rank counting, keys staged in smem. grid = QLEN/8, block = 256.
__global__ void k_rank(const int* __restrict__ startp, const int* __restrict__ lenp) {
    __shared__ unsigned long long sk[QLEN];
    const int start = *startp;
    const int ilen  = *lenp;
    const int t = threadIdx.x;
    for (int i = t; i < ilen; i += 256) sk[i] = g_key[start + i];
    __syncthreads();
    const int w = t >> 5, lane = t & 31;
    const int p = blockIdx.x * 8 + w;
    if (p >= QLEN) return;
    if (p < start || p >= start + ilen) {
        if (lane == 0) g_flag[p] = 1;
        return;
    }
    const int keep_k = (int)llrint((double)ilen * (1.0 - 0.3));
    const int i = p - start;
    const unsigned long long v = sk[i];
    int c = 0;
    for (int j = lane; j < ilen; j += 32) {
        const unsigned long long u = sk[j];
        c += (u > v) || (u == v && j < i);
    }
#pragma unroll
    for (int off = 16; off; off >>= 1) c += __shfl_down_sync(0xffffffffu, c, off);
    if (lane == 0) g_flag[p] = (c < keep_k) ? 1 : 0;
}

// K2b: compact via shuffle scan. single block, 1024 threads, 2 elems/thread.
__global__ void k_compact() {
    const int t = threadIdx.x;
    const int lane = t & 31, w = t >> 5;
    const int f0 = g_flag[2 * t];
    const int f1 = g_flag[2 * t + 1];
    const int sum = f0 + f1;
    int v = sum;
#pragma unroll
    for (int o = 1; o < 32; o <<= 1) {
        int n = __shfl_up_sync(0xffffffffu, v, o);
        if (lane >= o) v += n;
    }
    __shared__ int wsum[32];
    if (lane == 31) wsum[w] = v;
    __syncthreads();
    if (w == 0) {
        int x = wsum[lane];
#pragma unroll
        for (int o = 1; o < 32; o <<= 1) {
            int n = __shfl_up_sync(0xffffffffu, x, o);
            if (lane >= o) x += n;
        }
        wsum[lane] = x;
    }
    __syncthreads();
    const int base = (w ? wsum[w - 1] : 0) + v - sum;
    if (f0) g_keep[base] = 2 * t;
    if (f1) g_keep[base + f0] = 2 * t + 1;
    if (t == 1023) g_nkeep = wsum[31];
}

// K3: gather hs / pe rows. grid = (QLEN, 2), block = 256.
__global__ void k_gather_rows(const float* __restrict__ hs,
                              const float* __restrict__ pe,
                              float* __restrict__ out) {
    const int nk = g_nkeep;
    const int r  = blockIdx.x;
    if (r >= nk) return;
    const int srcrow = g_keep[r];
    const float* sp = (blockIdx.y ? pe : hs) + (size_t)srcrow * HID;
    float* dp = out + (size_t)blockIdx.y * nk * HID + (size_t)r * HID;
    const float4* s4 = reinterpret_cast<const float4*>(sp);
    float4* d4 = reinterpret_cast<float4*>(dp);
#pragma unroll 4
    for (int i = threadIdx.x; i < HID / 4; i += 256) d4[i] = s4[i];
}

// K4: mask gather, smem-staged source row. grid = QLEN, block = 512.
__global__ void k_gather_mask(const float* __restrict__ mask,
                              float* __restrict__ out) {
    __shared__ float srow[QLEN];
    const int nk = g_nkeep;
    const int r = blockIdx.x;
    if (r >= nk) return;
    const int t = threadIdx.x;
    const float* mp = mask + (size_t)g_keep[r] * QLEN;
#pragma unroll
    for (int i = t; i < QLEN; i += 512) srow[i] = mp[i];
    __syncthreads();
    const size_t base = 2ull * (size_t)nk * HID + (size_t)r * nk;
    for (int c = t; c < nk; c += 512)
        out[base + c] = srow[g_keep[c]];
}

extern "C" void kernel_launch(void* const* d_in, const int* in_sizes, int n_in,
                              void* d_out, int out_size) {
    const float* hs   = (const float*)d_in[0];
    const float* pe   = (const float*)d_in[1];
    const float* mask = (const float*)d_in[2];
    const float* attn = (const float*)d_in[3];
    const int* startp = (const int*)d_in[4];
    const int* lenp   = (const int*)d_in[5];
    float* out = (float*)d_out;

    k_partial<<<NCHUNK, 512>>>(attn);
    k_finalize_a<<<256, 256>>>();
    k_finalize_b<<<8, 256>>>();
    k_rank<<<QLEN / 8, 256>>>(startp, lenp);
    k_compact<<<1, 1024>>>();
    dim3 g3(QLEN, 2);
    k_gather_rows<<<g3, 256>>>(hs, pe, out);
    k_gather_mask<<<QLEN, 512>>>(mask, out);
}